// round 1
// baseline (speedup 1.0000x reference)
#include <cuda_runtime.h>
#include <cstdint>
#include <cstddef>

#define BATCH   16384
#define WIDTH   128
#define NNODES  12

#define BM 128
#define BN 128
#define BK 16
#define THREADS 256
#define AS_STRIDE (BM + 4)   // pad to dodge worst STS conflicts

// Scratch for node outputs 1..10 (node 11 goes to d_out, node 0 is x).
__device__ float g_scratch[10 * BATCH * WIDTH];

struct SmemBuf {
    float As[BK][AS_STRIDE];  // As[k][m]  (A transposed into smem)
    float Ws[BK][BN];         // Ws[k][n]
};

__device__ __forceinline__ unsigned long long fma2(unsigned long long a,
                                                   unsigned long long b,
                                                   unsigned long long c) {
    unsigned long long d;
    asm("fma.rn.f32x2 %0, %1, %2, %3;" : "=l"(d) : "l"(a), "l"(b), "l"(c));
    return d;
}
__device__ __forceinline__ unsigned long long pack2(float lo, float hi) {
    unsigned long long d;
    asm("mov.b64 %0, {%1, %2};" : "=l"(d) : "f"(lo), "f"(hi));
    return d;
}
__device__ __forceinline__ void unpack2(unsigned long long v, float& lo, float& hi) {
    asm("mov.b64 {%0, %1}, %2;" : "=f"(lo), "=f"(hi) : "l"(v));
}

__global__ __launch_bounds__(THREADS) void node_kernel(
    const float* __restrict__ x,
    const float* __restrict__ W,
    const float* __restrict__ b,
    float* __restrict__ final_out,
    int node)   // zero-based node index, 1..11
{
    __shared__ SmemBuf smem[2];

    const int tid  = threadIdx.x;
    const int tx   = tid & 15;   // column group 0..15
    const int ty   = tid >> 4;   // row group 0..15
    const int row0 = blockIdx.x * BM;

    const int estart  = node * (node - 1) / 2;
    const int nchunks = node * (WIDTH / BK);   // 8 chunks per edge

    // Accumulators: 4 row-pairs x 8 cols packed f32x2, plus running fp32 sum.
    unsigned long long acc2[4][8];
    float sum[8][8];
#pragma unroll
    for (int i = 0; i < 4; i++)
#pragma unroll
        for (int j = 0; j < 8; j++) acc2[i][j] = 0ull;
#pragma unroll
    for (int i = 0; i < 8; i++)
#pragma unroll
        for (int j = 0; j < 8; j++) sum[i][j] = 0.f;

    float4 areg[2], wreg[2];

    // ---- global load of chunk t into registers ----
    auto load_global = [&](int t) {
        const int e  = t >> 3;          // predecessor index u
        const int k0 = (t & 7) * BK;
        const float* Aptr = (e == 0) ? x : (g_scratch + (size_t)(e - 1) * BATCH * WIDTH);
        const float* Wptr = W + (size_t)(estart + e) * WIDTH * WIDTH;
#pragma unroll
        for (int i = 0; i < 2; i++) {
            const int task = i * THREADS + tid;
            const int m  = task >> 2;             // 0..127
            const int kq = (task & 3) * 4;        // 0,4,8,12
            areg[i] = *(const float4*)(Aptr + (size_t)(row0 + m) * WIDTH + k0 + kq);
            const int wk = task >> 5;             // 0..15
            const int wn = (task & 31) * 4;       // 0..124
            wreg[i] = *(const float4*)(Wptr + (size_t)(k0 + wk) * WIDTH + wn);
        }
    };

    auto store_smem = [&](int buf) {
        SmemBuf& s = smem[buf];
#pragma unroll
        for (int i = 0; i < 2; i++) {
            const int task = i * THREADS + tid;
            const int m  = task >> 2;
            const int kq = (task & 3) * 4;
            s.As[kq + 0][m] = areg[i].x;
            s.As[kq + 1][m] = areg[i].y;
            s.As[kq + 2][m] = areg[i].z;
            s.As[kq + 3][m] = areg[i].w;
            const int wk = task >> 5;
            const int wn = (task & 31) * 4;
            *(float4*)&s.Ws[wk][wn] = wreg[i];
        }
    };

    // Prologue: chunk 0
    load_global(0);
    store_smem(0);
    __syncthreads();

    for (int t = 0; t < nchunks; t++) {
        const int buf = t & 1;
        if (t + 1 < nchunks) load_global(t + 1);

        // ---- compute this chunk ----
        const SmemBuf& s = smem[buf];
#pragma unroll
        for (int k = 0; k < BK; k++) {
            // row pairs come out of the LDS.128 as aligned b64 pairs (no packs)
            ulonglong2 apLo = *(const ulonglong2*)&s.As[k][ty * 4];
            ulonglong2 apHi = *(const ulonglong2*)&s.As[k][64 + ty * 4];
            float4 w0 = *(const float4*)&s.Ws[k][tx * 4];
            float4 w1 = *(const float4*)&s.Ws[k][64 + tx * 4];

            unsigned long long ap[4] = { apLo.x, apLo.y, apHi.x, apHi.y };
            unsigned long long wp[8] = {
                pack2(w0.x, w0.x), pack2(w0.y, w0.y), pack2(w0.z, w0.z), pack2(w0.w, w0.w),
                pack2(w1.x, w1.x), pack2(w1.y, w1.y), pack2(w1.z, w1.z), pack2(w1.w, w1.w)
            };
#pragma unroll
            for (int rp = 0; rp < 4; rp++)
#pragma unroll
                for (int c = 0; c < 8; c++)
                    acc2[rp][c] = fma2(ap[rp], wp[c], acc2[rp][c]);
        }

        // ---- edge epilogue: bias + relu + running sum ----
        if ((t & 7) == 7) {
            const int e = t >> 3;
            const float* bptr = b + (size_t)(estart + e) * WIDTH;
            float4 b0 = *(const float4*)(bptr + tx * 4);
            float4 b1 = *(const float4*)(bptr + 64 + tx * 4);
            float bv[8] = { b0.x, b0.y, b0.z, b0.w, b1.x, b1.y, b1.z, b1.w };
#pragma unroll
            for (int rp = 0; rp < 4; rp++)
#pragma unroll
                for (int c = 0; c < 8; c++) {
                    float lo, hi;
                    unpack2(acc2[rp][c], lo, hi);
                    sum[2 * rp + 0][c] += fmaxf(lo + bv[c], 0.f);
                    sum[2 * rp + 1][c] += fmaxf(hi + bv[c], 0.f);
                    acc2[rp][c] = 0ull;
                }
        }

        if (t + 1 < nchunks) store_smem(buf ^ 1);
        __syncthreads();
    }

    // ---- write node output ----
    float* dst = (node == NNODES - 1)
                   ? final_out
                   : (g_scratch + (size_t)(node - 1) * BATCH * WIDTH);
#pragma unroll
    for (int i = 0; i < 8; i++) {
        // row mapping: acc pair rp covers local rows 2rp (lo), 2rp+1 (hi);
        // local rows 0..3 -> ty*4+0..3, rows 4..7 -> 64+ty*4+0..3
        const int rloc = (i < 4) ? (ty * 4 + i) : (64 + ty * 4 + (i - 4));
        const size_t r = (size_t)(row0 + rloc);
        float4 v0 = make_float4(sum[i][0], sum[i][1], sum[i][2], sum[i][3]);
        float4 v1 = make_float4(sum[i][4], sum[i][5], sum[i][6], sum[i][7]);
        *(float4*)(dst + r * WIDTH + tx * 4) = v0;
        *(float4*)(dst + r * WIDTH + 64 + tx * 4) = v1;
    }
}

extern "C" void kernel_launch(void* const* d_in, const int* in_sizes, int n_in,
                              void* d_out, int out_size) {
    const float* x = (const float*)d_in[0];   // [16384,128]
    const float* W = (const float*)d_in[1];   // [66,128,128]
    const float* b = (const float*)d_in[2];   // [66,128]
    float* out = (float*)d_out;               // [16384,128]

    dim3 grid(BATCH / BM);
    for (int node = 1; node < NNODES; node++) {
        node_kernel<<<grid, THREADS>>>(x, W, b, out, node);
    }
}

// round 3
// speedup vs baseline: 1.9087x; 1.9087x over previous
#include <cuda_runtime.h>
#include <cuda_bf16.h>
#include <cstdint>
#include <cstddef>

#define BATCH   16384
#define WIDTH   128
#define NNODES  12
#define NEDGES  66

#define BM 128
#define BK 64
#define THREADS 256
#define TILE_BYTES (128 * 128)            // 128 rows x 64 bf16 = 16 KB
#define STAGE_BYTES (4 * TILE_BYTES)      // Ahi, Alo, Whi, Wlo
#define SMEM_TOTAL (2 * STAGE_BYTES)      // double buffer = 128 KB

// ---------------- device scratch ----------------
__device__ __nv_bfloat16 g_Ahi[11u * BATCH * WIDTH];
__device__ __nv_bfloat16 g_Alo[11u * BATCH * WIDTH];
__device__ __nv_bfloat16 g_Whi[(size_t)NEDGES * WIDTH * WIDTH];  // [e][n][k] (transposed)
__device__ __nv_bfloat16 g_Wlo[(size_t)NEDGES * WIDTH * WIDTH];

// ---------------- PTX helpers ----------------
__device__ __forceinline__ uint32_t smem_u32(const void* p) {
    uint32_t a;
    asm("{ .reg .u64 t; cvta.to.shared.u64 t, %1; cvt.u32.u64 %0, t; }" : "=r"(a) : "l"(p));
    return a;
}
__device__ __forceinline__ void cp_async16(uint32_t dst, const void* src) {
    asm volatile("cp.async.cg.shared.global [%0], [%1], 16;" :: "r"(dst), "l"(src) : "memory");
}
__device__ __forceinline__ void cp_commit() {
    asm volatile("cp.async.commit_group;" ::: "memory");
}
__device__ __forceinline__ void cp_wait1() {
    asm volatile("cp.async.wait_group 1;" ::: "memory");
}
__device__ __forceinline__ void cp_wait0() {
    asm volatile("cp.async.wait_group 0;" ::: "memory");
}
__device__ __forceinline__ void ldsm4(uint32_t& r0, uint32_t& r1, uint32_t& r2, uint32_t& r3,
                                      uint32_t addr) {
    asm volatile("ldmatrix.sync.aligned.m8n8.x4.shared.b16 {%0,%1,%2,%3}, [%4];"
                 : "=r"(r0), "=r"(r1), "=r"(r2), "=r"(r3) : "r"(addr));
}
__device__ __forceinline__ void mma_bf16(float& d0, float& d1, float& d2, float& d3,
                                         uint32_t a0, uint32_t a1, uint32_t a2, uint32_t a3,
                                         uint32_t b0, uint32_t b1) {
    asm volatile(
        "mma.sync.aligned.m16n8k16.row.col.f32.bf16.bf16.f32 "
        "{%0,%1,%2,%3}, {%4,%5,%6,%7}, {%8,%9}, {%0,%1,%2,%3};"
        : "+f"(d0), "+f"(d1), "+f"(d2), "+f"(d3)
        : "r"(a0), "r"(a1), "r"(a2), "r"(a3), "r"(b0), "r"(b1));
}

// ---------------- conversion kernels ----------------
__global__ void conv_x_kernel(const float* __restrict__ x) {
    const int n = BATCH * WIDTH;
    for (int i = blockIdx.x * blockDim.x + threadIdx.x; i < n; i += gridDim.x * blockDim.x) {
        float v = x[i];
        __nv_bfloat16 h = __float2bfloat16(v);
        g_Ahi[i] = h;
        g_Alo[i] = __float2bfloat16(v - __bfloat162float(h));
    }
}

// W[e][k][n] fp32 -> g_W{hi,lo}[e][n][k] bf16 (transpose + split)
__global__ void conv_w_kernel(const float* __restrict__ W) {
    __shared__ float t[32][33];
    const int e  = blockIdx.x;
    const int ti = blockIdx.y;
    const int kt = (ti & 3) * 32;
    const int nt = (ti >> 2) * 32;
    const float* Wb = W + (size_t)e * WIDTH * WIDTH;
#pragma unroll
    for (int r = 0; r < 32; r += 8) {
        int k = kt + threadIdx.y + r;
        t[threadIdx.y + r][threadIdx.x] = Wb[k * WIDTH + nt + threadIdx.x];
    }
    __syncthreads();
    __nv_bfloat16* Hh = g_Whi + (size_t)e * WIDTH * WIDTH;
    __nv_bfloat16* Hl = g_Wlo + (size_t)e * WIDTH * WIDTH;
#pragma unroll
    for (int r = 0; r < 32; r += 8) {
        int n = nt + threadIdx.y + r;
        float v = t[threadIdx.x][threadIdx.y + r];
        __nv_bfloat16 h = __float2bfloat16(v);
        Hh[n * WIDTH + kt + threadIdx.x] = h;
        Hl[n * WIDTH + kt + threadIdx.x] = __float2bfloat16(v - __bfloat162float(h));
    }
}

// ---------------- main node kernel ----------------
// Per CTA: 128 rows x 128 cols. 8 warps: wm = wid&3 (M, 32 rows), wn = wid>>2 (N, 64 cols).
__global__ void __launch_bounds__(THREADS, 1) node_kernel(
    const float* __restrict__ bias,
    float* __restrict__ out,
    int node)
{
    extern __shared__ __align__(1024) char smem[];
    const uint32_t sbase = smem_u32(smem);

    const int tid  = threadIdx.x;
    const int wid  = tid >> 5;
    const int lane = tid & 31;
    const int v      = node;
    const int estart = v * (v - 1) / 2;
    const int row0   = blockIdx.x * BM;

    const int warp_moff = (wid & 3) * 32;
    const int warp_noff = (wid >> 2) * 64;

    const int nchunks = 2 * v;   // (edge, kc) pairs, kc in {0,1}

    // cp.async assignment: each thread covers row m = tid/2, chunks c = 4*(tid&1)+j
    const int ld_m = tid >> 1;
    const int ld_c0 = (tid & 1) * 4;

    auto load_chunk = [&](int t) {
        const int s  = t & 1;
        const int e  = t >> 1;
        const int kc = t & 1;
        const uint32_t stb = sbase + s * STAGE_BYTES;
        const size_t aoff = (size_t)e * (BATCH * WIDTH) + (size_t)(row0 + ld_m) * WIDTH + kc * 64;
        const size_t woff = (size_t)(estart + e) * (WIDTH * WIDTH) + (size_t)ld_m * WIDTH + kc * 64;
        const __nv_bfloat16* srcs[4] = { g_Ahi + aoff, g_Alo + aoff, g_Whi + woff, g_Wlo + woff };
#pragma unroll
        for (int tile = 0; tile < 4; tile++) {
            const uint32_t dbase = stb + tile * TILE_BYTES + ld_m * 128;
#pragma unroll
            for (int j = 0; j < 4; j++) {
                const int c = ld_c0 + j;
                cp_async16(dbase + ((c ^ (ld_m & 7)) << 4), srcs[tile] + c * 8);
            }
        }
    };

    float acc[2][8][4];   // per-edge accumulator
    float sum[2][8][4];   // running relu-sum
#pragma unroll
    for (int mi = 0; mi < 2; mi++)
#pragma unroll
        for (int ni = 0; ni < 8; ni++)
#pragma unroll
            for (int q = 0; q < 4; q++) sum[mi][ni][q] = 0.f;

    // prologue
    load_chunk(0);
    cp_commit();

    for (int t = 0; t < nchunks; t++) {
        if (t + 1 < nchunks) { load_chunk(t + 1); cp_commit(); cp_wait1(); }
        else                 { cp_wait0(); }
        __syncthreads();

        const int kc = t & 1;
        if (kc == 0) {
#pragma unroll
            for (int mi = 0; mi < 2; mi++)
#pragma unroll
                for (int ni = 0; ni < 8; ni++)
#pragma unroll
                    for (int q = 0; q < 4; q++) acc[mi][ni][q] = 0.f;
        }

        const uint32_t stb = sbase + (t & 1) * STAGE_BYTES;
        const uint32_t Ahi_b = stb;
        const uint32_t Alo_b = stb + TILE_BYTES;
        const uint32_t Whi_b = stb + 2 * TILE_BYTES;
        const uint32_t Wlo_b = stb + 3 * TILE_BYTES;

        const int q4   = lane >> 3;       // quadrant 0..3
        const int rsub = lane & 7;

#pragma unroll
        for (int ks = 0; ks < 4; ks++) {
            // ---- A fragments (hi, lo) for 2 m-tiles ----
            uint32_t ah[2][4], al[2][4];
            {
                const int arow = warp_moff + (q4 & 1) * 8 + rsub;
                const int ac   = ks * 2 + (q4 >> 1);
#pragma unroll
                for (int mi = 0; mi < 2; mi++) {
                    const int m = arow + mi * 16;
                    const uint32_t off = (uint32_t)(m * 128 + ((ac ^ (m & 7)) << 4));
                    ldsm4(ah[mi][0], ah[mi][1], ah[mi][2], ah[mi][3], Ahi_b + off);
                    ldsm4(al[mi][0], al[mi][1], al[mi][2], al[mi][3], Alo_b + off);
                }
            }
            // ---- B fragments (hi, lo) for 8 n-tiles, pairs via x4 ----
            uint32_t bh[4][4], bl[4][4];
            {
                const int bn0 = warp_noff + (q4 >> 1) * 8 + rsub;
                const int bc  = ks * 2 + (q4 & 1);
#pragma unroll
                for (int np = 0; np < 4; np++) {
                    const int n = bn0 + np * 16;
                    const uint32_t off = (uint32_t)(n * 128 + ((bc ^ (n & 7)) << 4));
                    ldsm4(bh[np][0], bh[np][1], bh[np][2], bh[np][3], Whi_b + off);
                    ldsm4(bl[np][0], bl[np][1], bl[np][2], bl[np][3], Wlo_b + off);
                }
            }
            // ---- 3-pass split MMA ----
#pragma unroll
            for (int mi = 0; mi < 2; mi++)
#pragma unroll
                for (int ni = 0; ni < 8; ni++) {
                    const int np = ni >> 1, h = (ni & 1) * 2;
                    float* d = acc[mi][ni];
                    mma_bf16(d[0], d[1], d[2], d[3],
                             ah[mi][0], ah[mi][1], ah[mi][2], ah[mi][3],
                             bh[np][h], bh[np][h + 1]);
                    mma_bf16(d[0], d[1], d[2], d[3],
                             ah[mi][0], ah[mi][1], ah[mi][2], ah[mi][3],
                             bl[np][h], bl[np][h + 1]);
                    mma_bf16(d[0], d[1], d[2], d[3],
                             al[mi][0], al[mi][1], al[mi][2], al[mi][3],
                             bh[np][h], bh[np][h + 1]);
                }
        }

        if (kc == 1) {
            // ---- per-edge epilogue: bias + relu + accumulate ----
            const int e = t >> 1;
            const float* bp = bias + (size_t)(estart + e) * WIDTH + warp_noff + 2 * (lane & 3);
#pragma unroll
            for (int ni = 0; ni < 8; ni++) {
                const float2 bb = *(const float2*)(bp + ni * 8);
#pragma unroll
                for (int mi = 0; mi < 2; mi++) {
                    sum[mi][ni][0] += fmaxf(acc[mi][ni][0] + bb.x, 0.f);
                    sum[mi][ni][1] += fmaxf(acc[mi][ni][1] + bb.y, 0.f);
                    sum[mi][ni][2] += fmaxf(acc[mi][ni][2] + bb.x, 0.f);
                    sum[mi][ni][3] += fmaxf(acc[mi][ni][3] + bb.y, 0.f);
                }
            }
        }
        __syncthreads();
    }

    // ---------------- writeout ----------------
    const int colb = warp_noff + 2 * (lane & 3);
    if (v == NNODES - 1) {
#pragma unroll
        for (int mi = 0; mi < 2; mi++) {
            const int r0 = row0 + warp_moff + mi * 16 + (lane >> 2);
#pragma unroll
            for (int ni = 0; ni < 8; ni++) {
                const int col = colb + ni * 8;
                *(float2*)(out + (size_t)r0 * WIDTH + col) =
                    make_float2(sum[mi][ni][0], sum[mi][ni][1]);
                *(float2*)(out + (size_t)(r0 + 8) * WIDTH + col) =
                    make_float2(sum[mi][ni][2], sum[mi][ni][3]);
            }
        }
    } else {
        const size_t nb = (size_t)v * (BATCH * WIDTH);
#pragma unroll
        for (int mi = 0; mi < 2; mi++) {
            const int r0 = row0 + warp_moff + mi * 16 + (lane >> 2);
#pragma unroll
            for (int ni = 0; ni < 8; ni++) {
                const int col = colb + ni * 8;
#pragma unroll
                for (int h = 0; h < 2; h++) {
                    const float s0 = sum[mi][ni][h * 2], s1 = sum[mi][ni][h * 2 + 1];
                    const __nv_bfloat16 h0 = __float2bfloat16(s0);
                    const __nv_bfloat16 h1 = __float2bfloat16(s1);
                    const __nv_bfloat16 l0 = __float2bfloat16(s0 - __bfloat162float(h0));
                    const __nv_bfloat16 l1 = __float2bfloat16(s1 - __bfloat162float(h1));
                    const size_t o = nb + (size_t)(r0 + h * 8) * WIDTH + col;
                    *(uint32_t*)&g_Ahi[o] = (uint32_t)__bfloat16_as_ushort(h0) |
                                            ((uint32_t)__bfloat16_as_ushort(h1) << 16);
                    *(uint32_t*)&g_Alo[o] = (uint32_t)__bfloat16_as_ushort(l0) |
                                            ((uint32_t)__bfloat16_as_ushort(l1) << 16);
                }
            }
        }
    }
}

// ---------------- launch ----------------
extern "C" void kernel_launch(void* const* d_in, const int* in_sizes, int n_in,
                              void* d_out, int out_size) {
    const float* x = (const float*)d_in[0];
    const float* W = (const float*)d_in[1];
    const float* b = (const float*)d_in[2];
    float* out = (float*)d_out;

    cudaFuncSetAttribute(node_kernel, cudaFuncAttributeMaxDynamicSharedMemorySize, SMEM_TOTAL);

    conv_x_kernel<<<512, 256>>>(x);
    conv_w_kernel<<<dim3(NEDGES, 16), dim3(32, 8)>>>(W);

    for (int v = 1; v < NNODES; v++) {
        node_kernel<<<BATCH / BM, THREADS, SMEM_TOTAL>>>(b, out, v);
    }
}

// round 4
// speedup vs baseline: 2.0429x; 1.0703x over previous
#include <cuda_runtime.h>
#include <cuda_bf16.h>
#include <cstdint>
#include <cstddef>

#define BATCH   16384
#define WIDTH   128
#define NNODES  12
#define NEDGES  66
#define NCHUNKS 132                       // sum over v of 2v

#define BM 128
#define THREADS 256
#define TILE_BYTES (128 * 128)            // 128 rows x 64 bf16 = 16 KB
#define STAGE_BYTES (4 * TILE_BYTES)      // Ahi, Alo, Whi, Wlo = 64 KB
#define NSTAGE 3
#define SMEM_TOTAL (NSTAGE * STAGE_BYTES) // 192 KB

// ---------------- device scratch ----------------
// slot 0 = x (converted); slots 1..10 = node outputs 1..10
__device__ __nv_bfloat16 g_Ahi[11u * BATCH * WIDTH];
__device__ __nv_bfloat16 g_Alo[11u * BATCH * WIDTH];
__device__ __nv_bfloat16 g_Whi[(size_t)NEDGES * WIDTH * WIDTH];  // [e][n][k] transposed
__device__ __nv_bfloat16 g_Wlo[(size_t)NEDGES * WIDTH * WIDTH];

// ---------------- PTX helpers ----------------
__device__ __forceinline__ uint32_t smem_u32(const void* p) {
    uint32_t a;
    asm("{ .reg .u64 t; cvta.to.shared.u64 t, %1; cvt.u32.u64 %0, t; }" : "=r"(a) : "l"(p));
    return a;
}
__device__ __forceinline__ void cp_async16(uint32_t dst, const void* src) {
    asm volatile("cp.async.cg.shared.global [%0], [%1], 16;" :: "r"(dst), "l"(src) : "memory");
}
__device__ __forceinline__ void cp_commit() {
    asm volatile("cp.async.commit_group;" ::: "memory");
}
__device__ __forceinline__ void cp_wait1() {
    asm volatile("cp.async.wait_group 1;" ::: "memory");
}
__device__ __forceinline__ void ldsm4(uint32_t& r0, uint32_t& r1, uint32_t& r2, uint32_t& r3,
                                      uint32_t addr) {
    asm volatile("ldmatrix.sync.aligned.m8n8.x4.shared.b16 {%0,%1,%2,%3}, [%4];"
                 : "=r"(r0), "=r"(r1), "=r"(r2), "=r"(r3) : "r"(addr));
}
__device__ __forceinline__ void mma_bf16(float& d0, float& d1, float& d2, float& d3,
                                         uint32_t a0, uint32_t a1, uint32_t a2, uint32_t a3,
                                         uint32_t b0, uint32_t b1) {
    asm volatile(
        "mma.sync.aligned.m16n8k16.row.col.f32.bf16.bf16.f32 "
        "{%0,%1,%2,%3}, {%4,%5,%6,%7}, {%8,%9}, {%0,%1,%2,%3};"
        : "+f"(d0), "+f"(d1), "+f"(d2), "+f"(d3)
        : "r"(a0), "r"(a1), "r"(a2), "r"(a3), "r"(b0), "r"(b1));
}

// ---------------- conversion kernels ----------------
__global__ void conv_x_kernel(const float* __restrict__ x) {
    const int n = BATCH * WIDTH;
    for (int i = blockIdx.x * blockDim.x + threadIdx.x; i < n; i += gridDim.x * blockDim.x) {
        float v = x[i];
        __nv_bfloat16 h = __float2bfloat16(v);
        g_Ahi[i] = h;
        g_Alo[i] = __float2bfloat16(v - __bfloat162float(h));
    }
}

// W[e][k][n] fp32 -> g_W{hi,lo}[e][n][k] bf16 (transpose + split)
__global__ void conv_w_kernel(const float* __restrict__ W) {
    __shared__ float t[32][33];
    const int e  = blockIdx.x;
    const int ti = blockIdx.y;
    const int kt = (ti & 3) * 32;
    const int nt = (ti >> 2) * 32;
    const float* Wb = W + (size_t)e * WIDTH * WIDTH;
#pragma unroll
    for (int r = 0; r < 32; r += 8) {
        int k = kt + threadIdx.y + r;
        t[threadIdx.y + r][threadIdx.x] = Wb[k * WIDTH + nt + threadIdx.x];
    }
    __syncthreads();
    __nv_bfloat16* Hh = g_Whi + (size_t)e * WIDTH * WIDTH;
    __nv_bfloat16* Hl = g_Wlo + (size_t)e * WIDTH * WIDTH;
#pragma unroll
    for (int r = 0; r < 32; r += 8) {
        int n = nt + threadIdx.y + r;
        float v = t[threadIdx.x][threadIdx.y + r];
        __nv_bfloat16 h = __float2bfloat16(v);
        Hh[n * WIDTH + kt + threadIdx.x] = h;
        Hl[n * WIDTH + kt + threadIdx.x] = __float2bfloat16(v - __bfloat162float(h));
    }
}

// chunk cursor: iterates (v, e, kc) over all 132 chunks
struct Cursor {
    int v, e, kc, w;   // w = global edge index = v(v-1)/2 + e
    __device__ __forceinline__ void init() { v = 1; e = 0; kc = 0; w = 0; }
    __device__ __forceinline__ void advance() {
        if (kc == 0) { kc = 1; return; }
        kc = 0; e++; w++;
        if (e == v) { e = 0; v++; w = v * (v - 1) / 2; }
    }
};

// ---------------- fused kernel: all 11 nodes, one launch ----------------
__global__ void __launch_bounds__(THREADS, 1) node_fused_kernel(
    const float* __restrict__ bias,
    float* __restrict__ out)
{
    extern __shared__ __align__(1024) char smem[];
    const uint32_t sbase = smem_u32(smem);

    const int tid  = threadIdx.x;
    const int lane = tid & 31;
    const int wid  = tid >> 5;
    const int row0 = blockIdx.x * BM;

    const int warp_moff = (wid & 3) * 32;
    const int warp_noff = (wid >> 2) * 64;

    // cp.async assignment: thread covers row m = tid/2, 16B chunks c = 4*(tid&1)+j
    const int ld_m  = tid >> 1;
    const int ld_c0 = (tid & 1) * 4;

    auto load_chunk = [&](const Cursor& c, int stage) {
        const uint32_t stb = sbase + stage * STAGE_BYTES;
        const size_t aoff = (size_t)c.e * (BATCH * WIDTH) + (size_t)(row0 + ld_m) * WIDTH + c.kc * 64;
        const size_t woff = (size_t)c.w * (WIDTH * WIDTH) + (size_t)ld_m * WIDTH + c.kc * 64;
        const __nv_bfloat16* srcs[4] = { g_Ahi + aoff, g_Alo + aoff, g_Whi + woff, g_Wlo + woff };
#pragma unroll
        for (int tile = 0; tile < 4; tile++) {
            const uint32_t dbase = stb + tile * TILE_BYTES + ld_m * 128;
#pragma unroll
            for (int j = 0; j < 4; j++) {
                const int cc = ld_c0 + j;
                cp_async16(dbase + ((cc ^ (ld_m & 7)) << 4), srcs[tile] + cc * 8);
            }
        }
    };

    float acc[2][8][4];
    float sum[2][8][4];

    Cursor cs; cs.init();
    Cursor pf; pf.init();

    // prologue: prefetch chunks 0, 1
    load_chunk(pf, 0); cp_commit(); pf.advance();
    load_chunk(pf, 1); cp_commit(); pf.advance();

    for (int g = 0; g < NCHUNKS; g++) {
        cp_wait1();            // stage g%3 ready
        __syncthreads();       // all threads see it; all done with stage (g-1)%3

        // prefetch chunk g+2 into stage (g+2)%3 (== (g-1)%3, now free)
        if (g + 2 < NCHUNKS) { load_chunk(pf, (g + 2) % NSTAGE); pf.advance(); }
        cp_commit();           // keep group accounting aligned (may be empty)

        // zero accumulators at edge start / node start
        if (cs.kc == 0) {
#pragma unroll
            for (int mi = 0; mi < 2; mi++)
#pragma unroll
                for (int ni = 0; ni < 8; ni++)
#pragma unroll
                    for (int q = 0; q < 4; q++) acc[mi][ni][q] = 0.f;
            if (cs.e == 0) {
#pragma unroll
                for (int mi = 0; mi < 2; mi++)
#pragma unroll
                    for (int ni = 0; ni < 8; ni++)
#pragma unroll
                        for (int q = 0; q < 4; q++) sum[mi][ni][q] = 0.f;
            }
        }

        const uint32_t stb = sbase + (g % NSTAGE) * STAGE_BYTES;
        const uint32_t Ahi_b = stb;
        const uint32_t Alo_b = stb + TILE_BYTES;
        const uint32_t Whi_b = stb + 2 * TILE_BYTES;
        const uint32_t Wlo_b = stb + 3 * TILE_BYTES;

        const int q4   = lane >> 3;
        const int rsub = lane & 7;

#pragma unroll
        for (int ks = 0; ks < 4; ks++) {
            uint32_t ah[2][4], al[2][4];
            {
                const int arow = warp_moff + (q4 & 1) * 8 + rsub;
                const int ac   = ks * 2 + (q4 >> 1);
#pragma unroll
                for (int mi = 0; mi < 2; mi++) {
                    const int m = arow + mi * 16;
                    const uint32_t off = (uint32_t)(m * 128 + ((ac ^ (m & 7)) << 4));
                    ldsm4(ah[mi][0], ah[mi][1], ah[mi][2], ah[mi][3], Ahi_b + off);
                    ldsm4(al[mi][0], al[mi][1], al[mi][2], al[mi][3], Alo_b + off);
                }
            }
            uint32_t bh[4][4], bl[4][4];
            {
                const int bn0 = warp_noff + (q4 >> 1) * 8 + rsub;
                const int bc  = ks * 2 + (q4 & 1);
#pragma unroll
                for (int np = 0; np < 4; np++) {
                    const int n = bn0 + np * 16;
                    const uint32_t off = (uint32_t)(n * 128 + ((bc ^ (n & 7)) << 4));
                    ldsm4(bh[np][0], bh[np][1], bh[np][2], bh[np][3], Whi_b + off);
                    ldsm4(bl[np][0], bl[np][1], bl[np][2], bl[np][3], Wlo_b + off);
                }
            }
#pragma unroll
            for (int mi = 0; mi < 2; mi++)
#pragma unroll
                for (int ni = 0; ni < 8; ni++) {
                    const int np = ni >> 1, h = (ni & 1) * 2;
                    float* d = acc[mi][ni];
                    mma_bf16(d[0], d[1], d[2], d[3],
                             ah[mi][0], ah[mi][1], ah[mi][2], ah[mi][3],
                             bh[np][h], bh[np][h + 1]);
                    mma_bf16(d[0], d[1], d[2], d[3],
                             ah[mi][0], ah[mi][1], ah[mi][2], ah[mi][3],
                             bl[np][h], bl[np][h + 1]);
                    mma_bf16(d[0], d[1], d[2], d[3],
                             al[mi][0], al[mi][1], al[mi][2], al[mi][3],
                             bh[np][h], bh[np][h + 1]);
                }
        }

        if (cs.kc == 1) {
            // per-edge epilogue: bias + relu + accumulate
            const float* bp = bias + (size_t)cs.w * WIDTH + warp_noff + 2 * (lane & 3);
#pragma unroll
            for (int ni = 0; ni < 8; ni++) {
                const float2 bb = *(const float2*)(bp + ni * 8);
#pragma unroll
                for (int mi = 0; mi < 2; mi++) {
                    sum[mi][ni][0] += fmaxf(acc[mi][ni][0] + bb.x, 0.f);
                    sum[mi][ni][1] += fmaxf(acc[mi][ni][1] + bb.y, 0.f);
                    sum[mi][ni][2] += fmaxf(acc[mi][ni][2] + bb.x, 0.f);
                    sum[mi][ni][3] += fmaxf(acc[mi][ni][3] + bb.y, 0.f);
                }
            }

            if (cs.e == cs.v - 1) {
                // ---- node writeout ----
                const int colb = warp_noff + 2 * (lane & 3);
                if (cs.v == NNODES - 1) {
#pragma unroll
                    for (int mi = 0; mi < 2; mi++) {
                        const int r0 = row0 + warp_moff + mi * 16 + (lane >> 2);
#pragma unroll
                        for (int ni = 0; ni < 8; ni++) {
                            const int col = colb + ni * 8;
                            *(float2*)(out + (size_t)r0 * WIDTH + col) =
                                make_float2(sum[mi][ni][0], sum[mi][ni][1]);
                            *(float2*)(out + (size_t)(r0 + 8) * WIDTH + col) =
                                make_float2(sum[mi][ni][2], sum[mi][ni][3]);
                        }
                    }
                } else {
                    const size_t nb = (size_t)cs.v * (BATCH * WIDTH);
#pragma unroll
                    for (int mi = 0; mi < 2; mi++) {
                        const int r0 = row0 + warp_moff + mi * 16 + (lane >> 2);
#pragma unroll
                        for (int ni = 0; ni < 8; ni++) {
                            const int col = colb + ni * 8;
#pragma unroll
                            for (int h = 0; h < 2; h++) {
                                const float s0 = sum[mi][ni][h * 2];
                                const float s1 = sum[mi][ni][h * 2 + 1];
                                const __nv_bfloat16 h0 = __float2bfloat16(s0);
                                const __nv_bfloat16 h1 = __float2bfloat16(s1);
                                const __nv_bfloat16 l0 = __float2bfloat16(s0 - __bfloat162float(h0));
                                const __nv_bfloat16 l1 = __float2bfloat16(s1 - __bfloat162float(h1));
                                const size_t o = nb + (size_t)(r0 + h * 8) * WIDTH + col;
                                *(uint32_t*)&g_Ahi[o] = (uint32_t)__bfloat16_as_ushort(h0) |
                                                        ((uint32_t)__bfloat16_as_ushort(h1) << 16);
                                *(uint32_t*)&g_Alo[o] = (uint32_t)__bfloat16_as_ushort(l0) |
                                                        ((uint32_t)__bfloat16_as_ushort(l1) << 16);
                            }
                        }
                    }
                }
            }
        }

        cs.advance();
    }
}

// ---------------- launch ----------------
extern "C" void kernel_launch(void* const* d_in, const int* in_sizes, int n_in,
                              void* d_out, int out_size) {
    const float* x = (const float*)d_in[0];
    const float* W = (const float*)d_in[1];
    const float* b = (const float*)d_in[2];
    float* out = (float*)d_out;

    cudaFuncSetAttribute(node_fused_kernel,
                         cudaFuncAttributeMaxDynamicSharedMemorySize, SMEM_TOTAL);

    conv_x_kernel<<<512, 256>>>(x);
    conv_w_kernel<<<dim3(NEDGES, 16), dim3(32, 8)>>>(W);
    node_fused_kernel<<<BATCH / BM, THREADS, SMEM_TOTAL>>>(b, out);
}

// round 5
// speedup vs baseline: 2.4550x; 1.2017x over previous
#include <cuda_runtime.h>
#include <cuda_bf16.h>
#include <cstdint>
#include <cstddef>

#define BATCH   16384
#define WIDTH   128
#define NNODES  12
#define NEDGES  66
#define NCHUNKS 132                       // sum over v of 2v

#define BM 128
#define THREADS 512
#define TILE_BYTES (128 * 128)            // 128 rows x 64 bf16 = 16 KB
#define STAGE_BYTES (4 * TILE_BYTES)      // Ahi, Alo, Whi, Wlo = 64 KB
#define NSTAGE 3
#define SMEM_TOTAL (NSTAGE * STAGE_BYTES) // 192 KB

// ---------------- device scratch ----------------
// slot 0 = x (converted); slots 1..10 = node outputs 1..10
__device__ __nv_bfloat16 g_Ahi[11u * BATCH * WIDTH];
__device__ __nv_bfloat16 g_Alo[11u * BATCH * WIDTH];
__device__ __nv_bfloat16 g_Whi[(size_t)NEDGES * WIDTH * WIDTH];  // [e][n][k] transposed
__device__ __nv_bfloat16 g_Wlo[(size_t)NEDGES * WIDTH * WIDTH];

// ---------------- PTX helpers ----------------
__device__ __forceinline__ uint32_t smem_u32(const void* p) {
    uint32_t a;
    asm("{ .reg .u64 t; cvta.to.shared.u64 t, %1; cvt.u32.u64 %0, t; }" : "=r"(a) : "l"(p));
    return a;
}
__device__ __forceinline__ void cp_async16(uint32_t dst, const void* src) {
    asm volatile("cp.async.cg.shared.global [%0], [%1], 16;" :: "r"(dst), "l"(src) : "memory");
}
__device__ __forceinline__ void cp_commit() {
    asm volatile("cp.async.commit_group;" ::: "memory");
}
__device__ __forceinline__ void cp_wait1() {
    asm volatile("cp.async.wait_group 1;" ::: "memory");
}
__device__ __forceinline__ void ldsm4(uint32_t& r0, uint32_t& r1, uint32_t& r2, uint32_t& r3,
                                      uint32_t addr) {
    asm volatile("ldmatrix.sync.aligned.m8n8.x4.shared.b16 {%0,%1,%2,%3}, [%4];"
                 : "=r"(r0), "=r"(r1), "=r"(r2), "=r"(r3) : "r"(addr));
}
__device__ __forceinline__ void mma_bf16(float& d0, float& d1, float& d2, float& d3,
                                         uint32_t a0, uint32_t a1, uint32_t a2, uint32_t a3,
                                         uint32_t b0, uint32_t b1) {
    asm volatile(
        "mma.sync.aligned.m16n8k16.row.col.f32.bf16.bf16.f32 "
        "{%0,%1,%2,%3}, {%4,%5,%6,%7}, {%8,%9}, {%0,%1,%2,%3};"
        : "+f"(d0), "+f"(d1), "+f"(d2), "+f"(d3)
        : "r"(a0), "r"(a1), "r"(a2), "r"(a3), "r"(b0), "r"(b1));
}

// ---------------- conversion kernels ----------------
__global__ void conv_x_kernel(const float* __restrict__ x) {
    const int n = BATCH * WIDTH;
    for (int i = blockIdx.x * blockDim.x + threadIdx.x; i < n; i += gridDim.x * blockDim.x) {
        float v = x[i];
        __nv_bfloat16 h = __float2bfloat16(v);
        g_Ahi[i] = h;
        g_Alo[i] = __float2bfloat16(v - __bfloat162float(h));
    }
}

// W[e][k][n] fp32 -> g_W{hi,lo}[e][n][k] bf16 (transpose + split)
__global__ void conv_w_kernel(const float* __restrict__ W) {
    __shared__ float t[32][33];
    const int e  = blockIdx.x;
    const int ti = blockIdx.y;
    const int kt = (ti & 3) * 32;
    const int nt = (ti >> 2) * 32;
    const float* Wb = W + (size_t)e * WIDTH * WIDTH;
#pragma unroll
    for (int r = 0; r < 32; r += 8) {
        int k = kt + threadIdx.y + r;
        t[threadIdx.y + r][threadIdx.x] = Wb[k * WIDTH + nt + threadIdx.x];
    }
    __syncthreads();
    __nv_bfloat16* Hh = g_Whi + (size_t)e * WIDTH * WIDTH;
    __nv_bfloat16* Hl = g_Wlo + (size_t)e * WIDTH * WIDTH;
#pragma unroll
    for (int r = 0; r < 32; r += 8) {
        int n = nt + threadIdx.y + r;
        float v = t[threadIdx.x][threadIdx.y + r];
        __nv_bfloat16 h = __float2bfloat16(v);
        Hh[n * WIDTH + kt + threadIdx.x] = h;
        Hl[n * WIDTH + kt + threadIdx.x] = __float2bfloat16(v - __bfloat162float(h));
    }
}

// chunk cursor: iterates (v, e, kc) over all 132 chunks
struct Cursor {
    int v, e, kc, w;   // w = global edge index = v(v-1)/2 + e
    __device__ __forceinline__ void init() { v = 1; e = 0; kc = 0; w = 0; }
    __device__ __forceinline__ void advance() {
        if (kc == 0) { kc = 1; return; }
        kc = 0; e++; w++;
        if (e == v) { e = 0; v++; w = v * (v - 1) / 2; }
    }
};

// ---------------- fused kernel: all 11 nodes, one launch ----------------
// 16 warps in a 4x4 grid; warp tile 32 (M) x 32 (N).
__global__ void __launch_bounds__(THREADS, 1) node_fused_kernel(
    const float* __restrict__ bias,
    float* __restrict__ out)
{
    extern __shared__ __align__(1024) char smem[];
    const uint32_t sbase = smem_u32(smem);

    const int tid  = threadIdx.x;
    const int lane = tid & 31;
    const int wid  = tid >> 5;
    const int row0 = blockIdx.x * BM;

    const int warp_moff = (wid & 3) * 32;
    const int warp_noff = (wid >> 2) * 32;

    // cp.async: thread covers row m = tid/4, 16B chunks c = 2*(tid&3)+j (j<2)
    const int ld_m  = tid >> 2;
    const int ld_c0 = (tid & 3) * 2;

    auto load_chunk = [&](const Cursor& c, int stage) {
        const uint32_t stb = sbase + stage * STAGE_BYTES;
        const size_t aoff = (size_t)c.e * (BATCH * WIDTH) + (size_t)(row0 + ld_m) * WIDTH + c.kc * 64;
        const size_t woff = (size_t)c.w * (WIDTH * WIDTH) + (size_t)ld_m * WIDTH + c.kc * 64;
        const __nv_bfloat16* srcs[4] = { g_Ahi + aoff, g_Alo + aoff, g_Whi + woff, g_Wlo + woff };
#pragma unroll
        for (int tile = 0; tile < 4; tile++) {
            const uint32_t dbase = stb + tile * TILE_BYTES + ld_m * 128;
#pragma unroll
            for (int j = 0; j < 2; j++) {
                const int cc = ld_c0 + j;
                cp_async16(dbase + ((cc ^ (ld_m & 7)) << 4), srcs[tile] + cc * 8);
            }
        }
    };

    float acc[2][4][4];   // per-edge accumulator (2 m-tiles x 4 n8-groups)
    float sum[2][4][4];   // running relu-sum

    Cursor cs; cs.init();
    Cursor pf; pf.init();

    // prologue: prefetch chunks 0, 1
    load_chunk(pf, 0); cp_commit(); pf.advance();
    load_chunk(pf, 1); cp_commit(); pf.advance();

    for (int g = 0; g < NCHUNKS; g++) {
        cp_wait1();            // stage g%3 ready
        __syncthreads();       // everyone sees it; stage (g-1)%3 fully consumed

        if (g + 2 < NCHUNKS) { load_chunk(pf, (g + 2) % NSTAGE); pf.advance(); }
        cp_commit();

        if (cs.kc == 0) {
#pragma unroll
            for (int mi = 0; mi < 2; mi++)
#pragma unroll
                for (int ni = 0; ni < 4; ni++)
#pragma unroll
                    for (int q = 0; q < 4; q++) acc[mi][ni][q] = 0.f;
            if (cs.e == 0) {
#pragma unroll
                for (int mi = 0; mi < 2; mi++)
#pragma unroll
                    for (int ni = 0; ni < 4; ni++)
#pragma unroll
                        for (int q = 0; q < 4; q++) sum[mi][ni][q] = 0.f;
            }
        }

        const uint32_t stb = sbase + (g % NSTAGE) * STAGE_BYTES;
        const uint32_t Ahi_b = stb;
        const uint32_t Alo_b = stb + TILE_BYTES;
        const uint32_t Whi_b = stb + 2 * TILE_BYTES;
        const uint32_t Wlo_b = stb + 3 * TILE_BYTES;

        const int q4   = lane >> 3;
        const int rsub = lane & 7;

#pragma unroll
        for (int ks = 0; ks < 4; ks++) {
            // ---- A fragments (hi, lo): 2 m16-tiles ----
            uint32_t ah[2][4], al[2][4];
            {
                const int arow = warp_moff + (q4 & 1) * 8 + rsub;
                const int ac   = ks * 2 + (q4 >> 1);
#pragma unroll
                for (int mi = 0; mi < 2; mi++) {
                    const int m = arow + mi * 16;
                    const uint32_t off = (uint32_t)(m * 128 + ((ac ^ (m & 7)) << 4));
                    ldsm4(ah[mi][0], ah[mi][1], ah[mi][2], ah[mi][3], Ahi_b + off);
                    ldsm4(al[mi][0], al[mi][1], al[mi][2], al[mi][3], Alo_b + off);
                }
            }
            // ---- B fragments (hi, lo): 2 n16-tiles ----
            uint32_t bh[2][4], bl[2][4];
            {
                const int bn0 = warp_noff + (q4 >> 1) * 8 + rsub;
                const int bc  = ks * 2 + (q4 & 1);
#pragma unroll
                for (int np = 0; np < 2; np++) {
                    const int n = bn0 + np * 16;
                    const uint32_t off = (uint32_t)(n * 128 + ((bc ^ (n & 7)) << 4));
                    ldsm4(bh[np][0], bh[np][1], bh[np][2], bh[np][3], Whi_b + off);
                    ldsm4(bl[np][0], bl[np][1], bl[np][2], bl[np][3], Wlo_b + off);
                }
            }
            // ---- 3-pass split MMA ----
#pragma unroll
            for (int mi = 0; mi < 2; mi++)
#pragma unroll
                for (int ni = 0; ni < 4; ni++) {
                    const int np = ni >> 1, h = (ni & 1) * 2;
                    float* d = acc[mi][ni];
                    mma_bf16(d[0], d[1], d[2], d[3],
                             ah[mi][0], ah[mi][1], ah[mi][2], ah[mi][3],
                             bh[np][h], bh[np][h + 1]);
                    mma_bf16(d[0], d[1], d[2], d[3],
                             ah[mi][0], ah[mi][1], ah[mi][2], ah[mi][3],
                             bl[np][h], bl[np][h + 1]);
                    mma_bf16(d[0], d[1], d[2], d[3],
                             al[mi][0], al[mi][1], al[mi][2], al[mi][3],
                             bh[np][h], bh[np][h + 1]);
                }
        }

        if (cs.kc == 1) {
            // per-edge epilogue: bias + relu + accumulate
            const float* bp = bias + (size_t)cs.w * WIDTH + warp_noff + 2 * (lane & 3);
#pragma unroll
            for (int ni = 0; ni < 4; ni++) {
                const float2 bb = *(const float2*)(bp + ni * 8);
#pragma unroll
                for (int mi = 0; mi < 2; mi++) {
                    sum[mi][ni][0] += fmaxf(acc[mi][ni][0] + bb.x, 0.f);
                    sum[mi][ni][1] += fmaxf(acc[mi][ni][1] + bb.y, 0.f);
                    sum[mi][ni][2] += fmaxf(acc[mi][ni][2] + bb.x, 0.f);
                    sum[mi][ni][3] += fmaxf(acc[mi][ni][3] + bb.y, 0.f);
                }
            }

            if (cs.e == cs.v - 1) {
                // ---- node writeout ----
                const int colb = warp_noff + 2 * (lane & 3);
                if (cs.v == NNODES - 1) {
#pragma unroll
                    for (int mi = 0; mi < 2; mi++) {
                        const int r0 = row0 + warp_moff + mi * 16 + (lane >> 2);
#pragma unroll
                        for (int ni = 0; ni < 4; ni++) {
                            const int col = colb + ni * 8;
                            *(float2*)(out + (size_t)r0 * WIDTH + col) =
                                make_float2(sum[mi][ni][0], sum[mi][ni][1]);
                            *(float2*)(out + (size_t)(r0 + 8) * WIDTH + col) =
                                make_float2(sum[mi][ni][2], sum[mi][ni][3]);
                        }
                    }
                } else {
                    const size_t nb = (size_t)cs.v * (BATCH * WIDTH);
#pragma unroll
                    for (int mi = 0; mi < 2; mi++) {
                        const int r0 = row0 + warp_moff + mi * 16 + (lane >> 2);
#pragma unroll
                        for (int ni = 0; ni < 4; ni++) {
                            const int col = colb + ni * 8;
#pragma unroll
                            for (int h = 0; h < 2; h++) {
                                const float s0 = sum[mi][ni][h * 2];
                                const float s1 = sum[mi][ni][h * 2 + 1];
                                const __nv_bfloat16 h0 = __float2bfloat16(s0);
                                const __nv_bfloat16 h1 = __float2bfloat16(s1);
                                const __nv_bfloat16 l0 = __float2bfloat16(s0 - __bfloat162float(h0));
                                const __nv_bfloat16 l1 = __float2bfloat16(s1 - __bfloat162float(h1));
                                const size_t o = nb + (size_t)(r0 + h * 8) * WIDTH + col;
                                *(uint32_t*)&g_Ahi[o] = (uint32_t)__bfloat16_as_ushort(h0) |
                                                        ((uint32_t)__bfloat16_as_ushort(h1) << 16);
                                *(uint32_t*)&g_Alo[o] = (uint32_t)__bfloat16_as_ushort(l0) |
                                                        ((uint32_t)__bfloat16_as_ushort(l1) << 16);
                            }
                        }
                    }
                }
            }
        }

        cs.advance();
    }
}

// ---------------- launch ----------------
extern "C" void kernel_launch(void* const* d_in, const int* in_sizes, int n_in,
                              void* d_out, int out_size) {
    const float* x = (const float*)d_in[0];
    const float* W = (const float*)d_in[1];
    const float* b = (const float*)d_in[2];
    float* out = (float*)d_out;

    cudaFuncSetAttribute(node_fused_kernel,
                         cudaFuncAttributeMaxDynamicSharedMemorySize, SMEM_TOTAL);

    conv_x_kernel<<<512, 256>>>(x);
    conv_w_kernel<<<dim3(NEDGES, 16), dim3(32, 8)>>>(W);
    node_fused_kernel<<<BATCH / BM, THREADS, SMEM_TOTAL>>>(b, out);
}